// round 16
// baseline (speedup 1.0000x reference)
#include <cuda_runtime.h>
#include <cuda_bf16.h>
#include <cuda_fp16.h>
#include <cstdint>
#include <cstddef>

#define D 128
#define N_BV 100000
#define N_LT 20000
#define N_CM 2000
#define N_DN 100000
#define E0_N 600000
#define E1_N 200000
#define E2_N 500000
#define E3_N 200000

// ---------------- scratch layout ----------------
constexpr size_t AL(size_t x) { return (x + 31) & ~size_t(31); }
constexpr size_t WS_USHORTS = 2 * 28 * 8192;
constexpr size_t WS_FLOATS  = WS_USHORTS / 2;

constexpr size_t OF_MEANBV = 0;                                   // fp16 payload (N_BV*128 halves)
constexpr size_t OF_AGG2   = AL(OF_MEANBV + (size_t)N_BV * 64);
constexpr size_t OF_AGG3   = AL(OF_AGG2 + (size_t)N_LT * D);
// ---- contiguous zero region: fts0..3, icnt0..3, lookback flags ----
constexpr size_t OF_FTS0   = AL(OF_AGG3 + (size_t)N_CM * D);
constexpr size_t OF_FTS1   = AL(OF_FTS0 + (size_t)N_BV * 16);
constexpr size_t OF_FTS2   = AL(OF_FTS1 + (size_t)N_BV * 16);
constexpr size_t OF_FTS3   = AL(OF_FTS2 + (size_t)N_LT * 16);
constexpr size_t OF_ICNT0  = AL(OF_FTS3 + (size_t)N_CM * 16);
constexpr size_t OF_ICNT1  = AL(OF_ICNT0 + N_BV);
constexpr size_t OF_ICNT2  = AL(OF_ICNT1 + N_BV);
constexpr size_t OF_ICNT3  = AL(OF_ICNT2 + N_LT);
constexpr size_t OF_P      = AL(OF_ICNT3 + N_CM);
constexpr size_t OF_ZERO_END = AL(OF_P + 512);
// ---- rest ----
constexpr size_t OF_HBV    = OF_ZERO_END;
constexpr size_t OF_HLT    = AL(OF_HBV + (size_t)N_BV * D);
constexpr size_t OF_HCM    = AL(OF_HLT + (size_t)N_LT * D);
constexpr size_t OF_ZLT    = AL(OF_HCM + (size_t)N_CM * D);   // fp16 payload
constexpr size_t OF_ZCM    = AL(OF_ZLT + (size_t)N_LT * D);   // fp16 payload
constexpr size_t OF_BBV    = AL(OF_ZCM + (size_t)N_CM * D);
constexpr size_t OF_BLT    = AL(OF_BBV + (size_t)N_BV * D);
constexpr size_t OF_BCM    = AL(OF_BLT + (size_t)N_LT * D);
constexpr size_t OF_DNH    = AL(OF_BCM + (size_t)N_CM * D);   // fp16 copy of h0_dn
constexpr size_t OF_HBVH   = AL(OF_DNH + (size_t)N_DN * 64);  // fp16 shadow of HBV
constexpr size_t OF_WS     = AL(OF_HBVH + (size_t)N_BV * 64);
constexpr size_t OF_BCOMB  = AL(OF_WS + WS_FLOATS);
constexpr size_t OF_RP0    = AL(OF_BCOMB + 256);
constexpr size_t OF_RP1    = AL(OF_RP0 + N_BV + 1);
constexpr size_t OF_RP2    = AL(OF_RP1 + N_BV + 1);
constexpr size_t OF_RP3    = AL(OF_RP2 + N_LT + 1);
constexpr size_t OF_CUR0   = AL(OF_RP3 + N_CM + 1);
constexpr size_t OF_CUR1   = AL(OF_CUR0 + N_BV);
constexpr size_t OF_CUR2   = AL(OF_CUR1 + N_BV);
constexpr size_t OF_CUR3   = AL(OF_CUR2 + N_LT);
constexpr size_t OF_SS0    = AL(OF_CUR3 + N_CM);
constexpr size_t OF_SS1    = AL(OF_SS0 + E0_N);
constexpr size_t OF_SS2    = AL(OF_SS1 + E1_N);
constexpr size_t OF_SS3    = AL(OF_SS2 + E2_N);
constexpr size_t SCRATCH_TOTAL = OF_SS3 + E3_N + 64;

__device__ __align__(128) float g_buf[SCRATCH_TOTAL];

// ---------------- dispatch constants ----------------
constexpr int CB0 = (E0_N + 255) / 256, CB1 = (E1_N + 255) / 256,
              CB2 = (E2_N + 255) / 256, CB3 = (E3_N + 255) / 256;
constexpr int CNT_BLKS = CB0 + CB1 + CB2 + CB3;
constexpr int SCT_BLKS = CNT_BLKS;
constexpr int FILL4 = (N_DN * D) / 4;
constexpr int FB = (FILL4 + 255) / 256;
constexpr int CV8 = (N_DN * D) / 8;                 // dn fp16 convert, 8 floats/thread
constexpr int CVB = (CV8 + 255) / 256;
constexpr int NB0 = (N_BV + 1023) / 1024, NB1 = NB0,
              NB2 = (N_LT + 1023) / 1024, NB3 = (N_CM + 1023) / 1024;
constexpr int SBB = NB0 + NB1 + NB2 + NB3;
constexpr int GB_BV = (N_BV + 127) / 128, GB_LT = (N_LT + 127) / 128,
              GB_CM = (N_CM + 127) / 128;
constexpr int CSRW_ALL = N_BV + N_LT + N_CM;
constexpr int CSRB_ALL = (CSRW_ALL + 7) / 8;
constexpr int BIAS_ROWS = N_BV + N_LT + N_CM;
constexpr int BIAS_BLKS = (BIAS_ROWS + 7) / 8;
constexpr int GEMM_SMEM = 53248;

// ---------------- helpers ----------------
__device__ __forceinline__ void red_add_v4(float* p, float4 v) {
    asm volatile("red.global.add.v4.f32 [%0], {%1, %2, %3, %4};"
                 :: "l"(p), "f"(v.x), "f"(v.y), "f"(v.z), "f"(v.w)
                 : "memory");
}
__device__ __forceinline__ unsigned short f2bf(float x) {
    __nv_bfloat16 h = __float2bfloat16(x);
    return *reinterpret_cast<unsigned short*>(&h);
}
__device__ __forceinline__ float bf2f(unsigned short u) {
    __nv_bfloat16 h;
    *reinterpret_cast<unsigned short*>(&h) = u;
    return __bfloat162float(h);
}
#define MMA_BF16(d, a0, a1, a2, a3, b0, b1) \
    asm volatile("mma.sync.aligned.m16n8k16.row.col.f32.bf16.bf16.f32 " \
                 "{%0,%1,%2,%3},{%4,%5,%6,%7},{%8,%9},{%0,%1,%2,%3};" \
                 : "+f"(d[0]), "+f"(d[1]), "+f"(d[2]), "+f"(d[3]) \
                 : "r"(a0), "r"(a1), "r"(a2), "r"(a3), "r"(b0), "r"(b1))

// ---------------- CSR gathers: MLP-4, fp32 and fp16 source variants ----------------
__device__ __forceinline__ float4 csr_gather_sum(const int* __restrict__ ss,
                                                 const float* __restrict__ X,
                                                 int b, int e, int lane)
{
    float4 acc = make_float4(0.f, 0.f, 0.f, 0.f);
    int j = b;
    for (; j + 4 <= e; j += 4) {
        int s0 = __ldg(ss + j),     s1 = __ldg(ss + j + 1);
        int s2 = __ldg(ss + j + 2), s3 = __ldg(ss + j + 3);
        float4 v0 = __ldg(reinterpret_cast<const float4*>(X + (size_t)s0 * 128) + lane);
        float4 v1 = __ldg(reinterpret_cast<const float4*>(X + (size_t)s1 * 128) + lane);
        float4 v2 = __ldg(reinterpret_cast<const float4*>(X + (size_t)s2 * 128) + lane);
        float4 v3 = __ldg(reinterpret_cast<const float4*>(X + (size_t)s3 * 128) + lane);
        acc.x += (v0.x + v1.x) + (v2.x + v3.x);
        acc.y += (v0.y + v1.y) + (v2.y + v3.y);
        acc.z += (v0.z + v1.z) + (v2.z + v3.z);
        acc.w += (v0.w + v1.w) + (v2.w + v3.w);
    }
    if (j + 2 <= e) {
        int s0 = __ldg(ss + j), s1 = __ldg(ss + j + 1);
        float4 v0 = __ldg(reinterpret_cast<const float4*>(X + (size_t)s0 * 128) + lane);
        float4 v1 = __ldg(reinterpret_cast<const float4*>(X + (size_t)s1 * 128) + lane);
        acc.x += v0.x + v1.x; acc.y += v0.y + v1.y;
        acc.z += v0.z + v1.z; acc.w += v0.w + v1.w;
        j += 2;
    }
    if (j < e) {
        int s0 = __ldg(ss + j);
        float4 v0 = __ldg(reinterpret_cast<const float4*>(X + (size_t)s0 * 128) + lane);
        acc.x += v0.x; acc.y += v0.y; acc.z += v0.z; acc.w += v0.w;
    }
    return acc;
}

__device__ __forceinline__ void hacc(float4& acc, uint2 u)
{
    float2 f01 = __half22float2(*reinterpret_cast<const __half2*>(&u.x));
    float2 f23 = __half22float2(*reinterpret_cast<const __half2*>(&u.y));
    acc.x += f01.x; acc.y += f01.y; acc.z += f23.x; acc.w += f23.y;
}

__device__ __forceinline__ float4 csr_gather_sum_h(const int* __restrict__ ss,
                                                   const __half* __restrict__ X,
                                                   int b, int e, int lane)
{
    float4 acc = make_float4(0.f, 0.f, 0.f, 0.f);
    int j = b;
    for (; j + 4 <= e; j += 4) {
        int s0 = __ldg(ss + j),     s1 = __ldg(ss + j + 1);
        int s2 = __ldg(ss + j + 2), s3 = __ldg(ss + j + 3);
        uint2 u0 = __ldg(reinterpret_cast<const uint2*>(X + (size_t)s0 * 128) + lane);
        uint2 u1 = __ldg(reinterpret_cast<const uint2*>(X + (size_t)s1 * 128) + lane);
        uint2 u2 = __ldg(reinterpret_cast<const uint2*>(X + (size_t)s2 * 128) + lane);
        uint2 u3 = __ldg(reinterpret_cast<const uint2*>(X + (size_t)s3 * 128) + lane);
        hacc(acc, u0); hacc(acc, u1); hacc(acc, u2); hacc(acc, u3);
    }
    if (j + 2 <= e) {
        int s0 = __ldg(ss + j), s1 = __ldg(ss + j + 1);
        uint2 u0 = __ldg(reinterpret_cast<const uint2*>(X + (size_t)s0 * 128) + lane);
        uint2 u1 = __ldg(reinterpret_cast<const uint2*>(X + (size_t)s1 * 128) + lane);
        hacc(acc, u0); hacc(acc, u1);
        j += 2;
    }
    if (j < e) {
        int s0 = __ldg(ss + j);
        uint2 u0 = __ldg(reinterpret_cast<const uint2*>(X + (size_t)s0 * 128) + lane);
        hacc(acc, u0);
    }
    return acc;
}

__device__ __forceinline__ float4 csr_gather_mean_h(const int* __restrict__ rp,
                                                    const int* __restrict__ ss,
                                                    const __half* __restrict__ X,
                                                    int w, int lane)
{
    int b = rp[w], e = rp[w + 1];
    float4 acc = csr_gather_sum_h(ss, X, b, e, lane);
    float inv = (e > b) ? 1.0f / (float)(e - b) : 0.0f;
    acc.x *= inv; acc.y *= inv; acc.z *= inv; acc.w *= inv;
    return acc;
}

__device__ __forceinline__ float4 csr_gather_mean(const int* __restrict__ rp,
                                                  const int* __restrict__ ss,
                                                  const float* __restrict__ X,
                                                  int w, int lane)
{
    int b = rp[w], e = rp[w + 1];
    float4 acc = csr_gather_sum(ss, X, b, e, lane);
    float inv = (e > b) ? 1.0f / (float)(e - b) : 0.0f;
    acc.x *= inv; acc.y *= inv; acc.z *= inv; acc.w *= inv;
    return acc;
}

// ================= prep_all: dn-fill + dn-fp16-convert + cnt_ft + wsplit + bcomb =================
__device__ __forceinline__ void cnt_ft_body(int i, const int* __restrict__ dst,
                                            const float* __restrict__ ft,
                                            int* __restrict__ icnt, float* __restrict__ fts, int E)
{
    if (i >= E) return;
    int d = dst[i];
    atomicAdd(icnt + d, 1);
    const float4* f = reinterpret_cast<const float4*>(ft) + (size_t)i * 4;
    float* o = fts + (size_t)d * 16;
    red_add_v4(o + 0,  f[0]);
    red_add_v4(o + 4,  f[1]);
    red_add_v4(o + 8,  f[2]);
    red_add_v4(o + 12, f[3]);
}

__global__ void prep_all(
    float* __restrict__ out_dn, const float* __restrict__ lnb3,
    const float* __restrict__ h0_dn, __half* __restrict__ dn_h,
    const int* dst0, const float* ft0, int* icnt0, float* fts0,
    const int* dst1, const float* ft1, int* icnt1, float* fts1,
    const int* dst2, const float* ft2, int* icnt2, float* fts2,
    const int* dst3, const float* ft3, int* icnt3, float* fts3,
    const float* __restrict__ convW, const float* __restrict__ convB,
    unsigned short* __restrict__ ws, float* __restrict__ bcomb)
{
    int bx = blockIdx.x, tid = threadIdx.x;
    if (bx < FB) {
        int idx = bx * 256 + tid;
        if (idx < FILL4) {
            float4 v = __ldg(reinterpret_cast<const float4*>(lnb3) + (idx & 31));
            reinterpret_cast<float4*>(out_dn)[idx] = v;
        }
        return;
    }
    bx -= FB;
    if (bx < CVB) {
        int idx = bx * 256 + tid;
        if (idx < CV8) {
            float4 a = __ldg(reinterpret_cast<const float4*>(h0_dn) + idx * 2);
            float4 b = __ldg(reinterpret_cast<const float4*>(h0_dn) + idx * 2 + 1);
            __half2 h0 = __floats2half2_rn(a.x, a.y);
            __half2 h1 = __floats2half2_rn(a.z, a.w);
            __half2 h2 = __floats2half2_rn(b.x, b.y);
            __half2 h3 = __floats2half2_rn(b.z, b.w);
            uint4 u;
            u.x = *reinterpret_cast<unsigned*>(&h0);
            u.y = *reinterpret_cast<unsigned*>(&h1);
            u.z = *reinterpret_cast<unsigned*>(&h2);
            u.w = *reinterpret_cast<unsigned*>(&h3);
            reinterpret_cast<uint4*>(dn_h)[idx] = u;
        }
        return;
    }
    bx -= CVB;
    if (bx < CNT_BLKS) {
        if (bx < CB0)                 cnt_ft_body(bx * 256 + tid, dst0, ft0, icnt0, fts0, E0_N);
        else if (bx < CB0 + CB1)      cnt_ft_body((bx - CB0) * 256 + tid, dst1, ft1, icnt1, fts1, E1_N);
        else if (bx < CB0 + CB1 + CB2) cnt_ft_body((bx - CB0 - CB1) * 256 + tid, dst2, ft2, icnt2, fts2, E2_N);
        else                          cnt_ft_body((bx - CB0 - CB1 - CB2) * 256 + tid, dst3, ft3, icnt3, fts3, E3_N);
        return;
    }
    bx -= CNT_BLKS;
    if (bx == 56) {
        if (tid < 256) {
            int l = tid >> 7, c = tid & 127;
            bcomb[tid] = convB[(l * 4 + 0) * 128 + c] + convB[(l * 4 + 1) * 128 + c];
        }
        return;
    }
    int l = bx / 28, c = bx % 28;
    const float* Wl = convW + (size_t)l * 4 * 32768;
    unsigned short* wsl = ws + (size_t)l * 28 * 8192;
    const float* W; const float* W2 = nullptr; int chunk; unsigned short* o;
    if (c < 4)       { W = Wl + 16384;             chunk = c;      o = wsl; }
    else if (c < 8)  { W = Wl + 32768 + 16384;     chunk = c - 4;  o = wsl + 4 * 8192; }
    else if (c < 12) { W = Wl; W2 = Wl + 32768;    chunk = c - 8;  o = wsl + 8 * 8192; }
    else if (c < 20) { W = Wl + 2 * 32768;         chunk = c - 12; o = wsl + 12 * 8192; }
    else             { W = Wl + 3 * 32768;         chunk = c - 20; o = wsl + 20 * 8192; }
    int k0 = chunk * 32;
    unsigned short* op = o + (size_t)chunk * 8192;
#pragma unroll
    for (int t = 0; t < 16; t++) {
        int e = tid + t * 256;
        int k = e >> 7;
        int n = e & 127;
        float w = W[(size_t)(k0 + k) * 128 + n];
        if (W2) w += W2[(size_t)(k0 + k) * 128 + n];
        unsigned short hi = f2bf(w);
        unsigned short lo = f2bf(w - bf2f(hi));
        int q = (k & 7) >> 1;
        int slot = k >> 3;
        int off = n * 32 + q * 8 + slot * 2 + (k & 1);
        op[off] = hi;
        op[4096 + off] = lo;
    }
}

// ================= scanbias_all: warp-lookback scan (4 arrays) + edge-bias =================
__global__ void scanbias_all(
    const int* i0, int* r0, int* c0,
    const int* i1, int* r1, int* c1,
    const int* i2, int* r2, int* c2,
    const int* i3, int* r3, int* c3,
    int* __restrict__ P,
    const float* __restrict__ fts0, const int* __restrict__ icnt0,
    const float* __restrict__ fts1, const int* __restrict__ icnt1,
    const float* __restrict__ fts2, const int* __restrict__ icnt2,
    const float* __restrict__ fts3, const int* __restrict__ icnt3,
    const float* __restrict__ emlpW, const float* __restrict__ emlpB,
    float* __restrict__ bias_bv, float* __restrict__ bias_lt, float* __restrict__ bias_cm)
{
    __shared__ int sh[1024];
    __shared__ float fb[8][32];
    __shared__ int s_off;
    int bx = blockIdx.x;
    if (bx < SBB) {
        const int* in; int* outp; int* cur; int n; int lb; int arr; int total;
        if (bx < NB0)                  { in = i0; outp = r0; cur = c0; n = N_BV; lb = bx; arr = 0; total = E0_N; }
        else if (bx < NB0 + NB1)       { in = i1; outp = r1; cur = c1; n = N_BV; lb = bx - NB0; arr = 1; total = E1_N; }
        else if (bx < NB0 + NB1 + NB2) { in = i2; outp = r2; cur = c2; n = N_LT; lb = bx - NB0 - NB1; arr = 2; total = E2_N; }
        else                           { in = i3; outp = r3; cur = c3; n = N_CM; lb = bx - NB0 - NB1 - NB2; arr = 3; total = E3_N; }
        int i = lb * 1024 + threadIdx.x;
        int v = (i < n) ? in[i] : 0;
        sh[threadIdx.x] = v;
        __syncthreads();
        for (int off = 1; off < 1024; off <<= 1) {
            int t = (threadIdx.x >= (unsigned)off) ? sh[threadIdx.x - off] : 0;
            __syncthreads();
            sh[threadIdx.x] += t;
            __syncthreads();
        }
        int incl = sh[threadIdx.x];
        volatile int* Pa = (volatile int*)(P + arr * 128);
        if (threadIdx.x == 1023) {
            __threadfence();
            Pa[lb] = sh[1023] + 1;
        }
        if (threadIdx.x < 32) {
            int off = 0;
            for (int j0 = 0; j0 < lb; j0 += 32) {
                int j = j0 + (int)threadIdx.x;
                int vv = 0;
                if (j < lb) {
                    do { vv = Pa[j]; } while (vv == 0);
                    vv -= 1;
                }
#pragma unroll
                for (int o = 16; o; o >>= 1) vv += __shfl_xor_sync(0xffffffffu, vv, o);
                off += vv;
            }
            if (threadIdx.x == 0) s_off = off;
        }
        __syncthreads();
        int off = s_off;
        if (i < n) {
            int ex = off + incl - v;
            outp[i] = ex;
            cur[i] = ex;
        }
        if (lb == 0 && threadIdx.x == 0) outp[n] = total;
        return;
    }
    // --- bias part ---
    int sub = threadIdx.x >> 7;
    int c = threadIdx.x & 127;
    int row = (bx - SBB) * 8 + sub;
    bool valid = row < BIAS_ROWS;
    if (valid) {
        if (row < N_BV) {
            if (c < 16) fb[sub][c] = fts0[(size_t)row * 16 + c];
            else if (c >= 32 && c < 48) fb[sub][c - 16] = fts1[(size_t)row * 16 + (c - 32)];
        } else if (row < N_BV + N_LT) {
            int r = row - N_BV;
            if (c < 16) fb[sub][c] = fts2[(size_t)r * 16 + c];
        } else {
            int r = row - N_BV - N_LT;
            if (c < 16) fb[sub][c] = fts3[(size_t)r * 16 + c];
        }
    }
    __syncthreads();
    if (!valid) return;
    if (row < N_BV) {
        int c0v = icnt0[row], c1v = icnt1[row];
        float i0v = (c0v > 0) ? 1.0f / (float)c0v : 0.0f;
        float i1v = (c1v > 0) ? 1.0f / (float)c1v : 0.0f;
        float a0 = 0.0f, a1 = 0.0f;
#pragma unroll
        for (int j = 0; j < 16; j++) {
            a0 = fmaf(fb[sub][j],      emlpW[j * 128 + c],        a0);
            a1 = fmaf(fb[sub][16 + j], emlpW[2048 + j * 128 + c], a1);
        }
        float a = a0 * i0v + a1 * i1v;
        if (c0v > 0) a += emlpB[c];
        if (c1v > 0) a += emlpB[128 + c];
        bias_bv[(size_t)row * 128 + c] = a;
    } else {
        const int* icnt; const float* W; const float* bml; float* outp; int r;
        if (row < N_BV + N_LT) {
            r = row - N_BV; icnt = icnt2;
            W = emlpW + 2 * 2048; bml = emlpB + 256; outp = bias_lt;
        } else {
            r = row - N_BV - N_LT; icnt = icnt3;
            W = emlpW + 3 * 2048; bml = emlpB + 384; outp = bias_cm;
        }
        int cv = icnt[r];
        float inv = (cv > 0) ? 1.0f / (float)cv : 0.0f;
        float a = 0.0f;
#pragma unroll
        for (int j = 0; j < 16; j++) a = fmaf(fb[sub][j], W[j * 128 + c], a);
        a *= inv;
        if (cv > 0) a += bml[c];
        outp[(size_t)r * 128 + c] = a;
    }
}

// ---------------- csr_all: cm first, then lt, then bv ----------------
// X3 is fp32 (layer1: h0_bv) or fp16 (layer2: hbv_h) per x3half.
__global__ __launch_bounds__(256) void csr_all_kernel(
    const int* __restrict__ rp0, const int* __restrict__ ss0, const __half* __restrict__ X0,
    const int* __restrict__ rp1, const int* __restrict__ ss1, const __half* __restrict__ X1,
    __half* __restrict__ mean_bv,
    const int* __restrict__ rp2, const int* __restrict__ ss2, const __half* __restrict__ X2,
    float* __restrict__ agg2, const float* __restrict__ lnb3, int l2mode,
    const int* __restrict__ rp3, const int* __restrict__ ss3,
    const float* __restrict__ X3f, const __half* __restrict__ X3h, int x3half,
    float* __restrict__ agg3)
{
    int gw = (int)((blockIdx.x * blockDim.x + threadIdx.x) >> 5);
    int lane = threadIdx.x & 31;
    if (gw < N_CM) {
        float4 a = x3half ? csr_gather_mean_h(rp3, ss3, X3h, gw, lane)
                          : csr_gather_mean(rp3, ss3, X3f, gw, lane);
        reinterpret_cast<float4*>(agg3 + (size_t)gw * 128)[lane] = a;
    } else if (gw < N_CM + N_LT) {
        int w = gw - N_CM;
        if (!l2mode) {
            float4 a = csr_gather_mean_h(rp2, ss2, X2, w, lane);
            reinterpret_cast<float4*>(agg2 + (size_t)w * 128)[lane] = a;
        } else {
            bool nz = rp2[w + 1] > rp2[w];
            float4 v = make_float4(0.f, 0.f, 0.f, 0.f);
            if (nz) v = __ldg(reinterpret_cast<const float4*>(lnb3) + lane);
            reinterpret_cast<float4*>(agg2 + (size_t)w * 128)[lane] = v;
        }
    } else if (gw < CSRW_ALL) {
        int w = gw - N_CM - N_LT;
        int b0 = rp0[w], e0 = rp0[w + 1];
        int b1 = rp1[w], e1 = rp1[w + 1];
        float4 a = csr_gather_sum_h(ss0, X0, b0, e0, lane);
        float4 b = csr_gather_sum_h(ss1, X1, b1, e1, lane);
        float ia = (e0 > b0) ? 1.0f / (float)(e0 - b0) : 0.0f;
        float ib = (e1 > b1) ? 1.0f / (float)(e1 - b1) : 0.0f;
        a.x = a.x * ia + b.x * ib;
        a.y = a.y * ia + b.y * ib;
        a.z = a.z * ia + b.z * ib;
        a.w = a.w * ia + b.w * ib;
        __half2 h01 = __floats2half2_rn(a.x, a.y);
        __half2 h23 = __floats2half2_rn(a.z, a.w);
        uint2 u;
        u.x = *reinterpret_cast<unsigned*>(&h01);
        u.y = *reinterpret_cast<unsigned*>(&h23);
        *reinterpret_cast<uint2*>(mean_bv + (size_t)w * 128 + lane * 4) = u;
    }
}

// ---------------- tensor-core split-bf16 GEMM core + fused epilogue ----------------
struct GP {
    const float* A1; const float* A2; int M;
    const unsigned short* wsp; int Kc;
    const float* bvec; const float* add1; const float* add2;
    const float* lng; const float* lnb;
    float* C;
    const unsigned short* zwsp;
    float* zC;          // fp16 buffer
    int halfC;          // write C as fp16
    int add1h;          // add1 is fp16
    float* hC;          // optional fp16 shadow copy of C
};

__device__ void gemm_core(int row0, const float* __restrict__ A1, const float* __restrict__ A2,
                          int M, const unsigned short* __restrict__ wsp, int Kc,
                          const float* __restrict__ bvec,
                          const float* __restrict__ add1, int add1h,
                          const float* __restrict__ add2,
                          const float* __restrict__ lng, const float* __restrict__ lnb,
                          float* __restrict__ C, int halfout, float* __restrict__ hC,
                          unsigned short* dsm)
{
    unsigned short (*Ah)[40]  = reinterpret_cast<unsigned short(*)[40]>(dsm);
    unsigned short (*Alo)[40] = reinterpret_cast<unsigned short(*)[40]>(dsm + 5120);
    unsigned short* Bh = dsm + 10240;
    unsigned short* Bl = dsm + 18432;

    int tid = threadIdx.x;
    int wid = tid >> 5, lane = tid & 31;

    float acc[16][4];
#pragma unroll
    for (int i = 0; i < 16; i++)
#pragma unroll
        for (int j = 0; j < 4; j++) acc[i][j] = 0.0f;

    for (int kc = 0; kc < Kc; kc++) {
        const float* Asrc = (kc < 4) ? A1 : A2;
        int kk = (kc & 3) * 32;
#pragma unroll
        for (int t = 0; t < 4; t++) {
            int i = tid + t * 256;
            int r = i >> 3;
            int kq = i & 7;
            int gr = row0 + r;
            float4 v = make_float4(0.f, 0.f, 0.f, 0.f);
            if (gr < M) v = *reinterpret_cast<const float4*>(Asrc + (size_t)gr * 128 + kk + kq * 4);
            unsigned short h0 = f2bf(v.x), h1 = f2bf(v.y), h2 = f2bf(v.z), h3 = f2bf(v.w);
            unsigned short l0 = f2bf(v.x - bf2f(h0)), l1 = f2bf(v.y - bf2f(h1));
            unsigned short l2 = f2bf(v.z - bf2f(h2)), l3 = f2bf(v.w - bf2f(h3));
            *reinterpret_cast<uint2*>(&Ah[r][kq * 4]) =
                make_uint2((uint32_t)h0 | ((uint32_t)h1 << 16), (uint32_t)h2 | ((uint32_t)h3 << 16));
            *reinterpret_cast<uint2*>(&Alo[r][kq * 4]) =
                make_uint2((uint32_t)l0 | ((uint32_t)l1 << 16), (uint32_t)l2 | ((uint32_t)l3 << 16));
        }
        const uint4* wp = reinterpret_cast<const uint4*>(wsp + (size_t)kc * 8192);
        uint4* bhv = reinterpret_cast<uint4*>(Bh);
        uint4* blv = reinterpret_cast<uint4*>(Bl);
#pragma unroll
        for (int t = 0; t < 2; t++) {
            int i = tid + t * 256;
            bhv[i] = wp[i];
            blv[i] = wp[512 + i];
        }
        __syncthreads();

        int ar = wid * 16 + (lane >> 2);
        int q2 = (lane & 3) * 2;
        uint32_t AHr[2][4], ALr[2][4];
#pragma unroll
        for (int ks = 0; ks < 2; ks++) {
            int ac = ks * 16 + q2;
            AHr[ks][0] = *reinterpret_cast<const uint32_t*>(&Ah[ar][ac]);
            AHr[ks][1] = *reinterpret_cast<const uint32_t*>(&Ah[ar + 8][ac]);
            AHr[ks][2] = *reinterpret_cast<const uint32_t*>(&Ah[ar][ac + 8]);
            AHr[ks][3] = *reinterpret_cast<const uint32_t*>(&Ah[ar + 8][ac + 8]);
            ALr[ks][0] = *reinterpret_cast<const uint32_t*>(&Alo[ar][ac]);
            ALr[ks][1] = *reinterpret_cast<const uint32_t*>(&Alo[ar + 8][ac]);
            ALr[ks][2] = *reinterpret_cast<const uint32_t*>(&Alo[ar][ac + 8]);
            ALr[ks][3] = *reinterpret_cast<const uint32_t*>(&Alo[ar + 8][ac + 8]);
        }
#pragma unroll
        for (int nt = 0; nt < 16; nt++) {
            int boff = (nt * 8 + (lane >> 2)) * 32 + (lane & 3) * 8;
            uint4 bh = *reinterpret_cast<const uint4*>(Bh + boff);
            uint4 bl = *reinterpret_cast<const uint4*>(Bl + boff);
            MMA_BF16(acc[nt], AHr[0][0], AHr[0][1], AHr[0][2], AHr[0][3], bh.x, bh.y);
            MMA_BF16(acc[nt], AHr[0][0], AHr[0][1], AHr[0][2], AHr[0][3], bl.x, bl.y);
            MMA_BF16(acc[nt], ALr[0][0], ALr[0][1], ALr[0][2], ALr[0][3], bh.x, bh.y);
            MMA_BF16(acc[nt], AHr[1][0], AHr[1][1], AHr[1][2], AHr[1][3], bh.z, bh.w);
            MMA_BF16(acc[nt], AHr[1][0], AHr[1][1], AHr[1][2], AHr[1][3], bl.z, bl.w);
            MMA_BF16(acc[nt], ALr[1][0], ALr[1][1], ALr[1][2], ALr[1][3], bh.z, bh.w);
        }
        __syncthreads();
    }

    int r1 = row0 + wid * 16 + (lane >> 2);
    int r2 = r1 + 8;
    int cb = (lane & 3) * 2;
    bool ok1 = r1 < M, ok2 = r2 < M;

    float s1 = 0.f, q1 = 0.f, s2 = 0.f, q2s = 0.f;
#pragma unroll
    for (int nt = 0; nt < 16; nt++) {
        int col = nt * 8 + cb;
        if (bvec) {
            float bx = bvec[col], by = bvec[col + 1];
            acc[nt][0] += bx; acc[nt][1] += by;
            acc[nt][2] += bx; acc[nt][3] += by;
        }
        if (add1) {
            if (add1h) {
                const __half* A1h = reinterpret_cast<const __half*>(add1);
                if (ok1) {
                    __half2 q = *reinterpret_cast<const __half2*>(A1h + (size_t)r1 * 128 + col);
                    float2 f = __half22float2(q);
                    acc[nt][0] += f.x; acc[nt][1] += f.y;
                }
                if (ok2) {
                    __half2 q = *reinterpret_cast<const __half2*>(A1h + (size_t)r2 * 128 + col);
                    float2 f = __half22float2(q);
                    acc[nt][2] += f.x; acc[nt][3] += f.y;
                }
            } else {
                if (ok1) {
                    float2 q = *reinterpret_cast<const float2*>(add1 + (size_t)r1 * 128 + col);
                    acc[nt][0] += q.x; acc[nt][1] += q.y;
                }
                if (ok2) {
                    float2 q = *reinterpret_cast<const float2*>(add1 + (size_t)r2 * 128 + col);
                    acc[nt][2] += q.x; acc[nt][3] += q.y;
                }
            }
        }
        if (add2) {
            if (ok1) {
                float2 q = *reinterpret_cast<const float2*>(add2 + (size_t)r1 * 128 + col);
                acc[nt][0] += q.x; acc[nt][1] += q.y;
            }
            if (ok2) {
                float2 q = *reinterpret_cast<const float2*>(add2 + (size_t)r2 * 128 + col);
                acc[nt][2] += q.x; acc[nt][3] += q.y;
            }
        }
        s1 += acc[nt][0] + acc[nt][1];
        q1 += acc[nt][0] * acc[nt][0] + acc[nt][1] * acc[nt][1];
        s2 += acc[nt][2] + acc[nt][3];
        q2s += acc[nt][2] * acc[nt][2] + acc[nt][3] * acc[nt][3];
    }

    float m1 = 0.f, rs1 = 1.f, m2 = 0.f, rs2 = 1.f;
    if (lng) {
#pragma unroll
        for (int off = 1; off < 4; off <<= 1) {
            s1 += __shfl_xor_sync(0xffffffffu, s1, off);
            q1 += __shfl_xor_sync(0xffffffffu, q1, off);
            s2 += __shfl_xor_sync(0xffffffffu, s2, off);
            q2s += __shfl_xor_sync(0xffffffffu, q2s, off);
        }
        m1 = s1 * (1.0f / 128.0f);
        rs1 = rsqrtf(q1 * (1.0f / 128.0f) - m1 * m1 + 1e-5f);
        m2 = s2 * (1.0f / 128.0f);
        rs2 = rsqrtf(q2s * (1.0f / 128.0f) - m2 * m2 + 1e-5f);
    }

#pragma unroll
    for (int nt = 0; nt < 16; nt++) {
        int col = nt * 8 + cb;
        float o0 = acc[nt][0], o1 = acc[nt][1], o2 = acc[nt][2], o3 = acc[nt][3];
        if (lng) {
            float gx = lng[col], gy = lng[col + 1];
            float bx = lnb[col], by = lnb[col + 1];
            o0 = (o0 - m1) * rs1 * gx + bx;
            o1 = (o1 - m1) * rs1 * gy + by;
            o2 = (o2 - m2) * rs2 * gx + bx;
            o3 = (o3 - m2) * rs2 * gy + by;
        }
        if (halfout) {
            __half* Ch = reinterpret_cast<__half*>(C);
            if (ok1) *reinterpret_cast<__half2*>(Ch + (size_t)r1 * 128 + col) = __floats2half2_rn(o0, o1);
            if (ok2) *reinterpret_cast<__half2*>(Ch + (size_t)r2 * 128 + col) = __floats2half2_rn(o2, o3);
        } else {
            if (ok1) *reinterpret_cast<float2*>(C + (size_t)r1 * 128 + col) = make_float2(o0, o1);
            if (ok2) *reinterpret_cast<float2*>(C + (size_t)r2 * 128 + col) = make_float2(o2, o3);
        }
        if (hC) {
            __half* H = reinterpret_cast<__half*>(hC);
            if (ok1) *reinterpret_cast<__half2*>(H + (size_t)r1 * 128 + col) = __floats2half2_rn(o0, o1);
            if (ok2) *reinterpret_cast<__half2*>(H + (size_t)r2 * 128 + col) = __floats2half2_rn(o2, o3);
        }
    }
}

__device__ void gemm_body(int blk, const GP& p, unsigned short* dsm)
{
    gemm_core(blk * 128, p.A1, p.A2, p.M, p.wsp, p.Kc,
              p.bvec, p.add1, p.add1h, p.add2, p.lng, p.lnb, p.C, p.halfC, p.hC, dsm);
    if (p.zwsp) {
        __threadfence_block();
        __syncthreads();
        gemm_core(blk * 128, p.C, nullptr, p.M, p.zwsp, 4,
                  nullptr, nullptr, 0, nullptr, nullptr, nullptr, p.zC, 1, nullptr, dsm);
    }
}

__global__ __launch_bounds__(256, 2) void gemm3_kernel(GP p0, GP p1, GP p2, int nb0, int nb1)
{
    extern __shared__ unsigned short dsm[];
    int bx = blockIdx.x;
    if (bx < nb0) gemm_body(bx, p0, dsm);
    else if (bx < nb0 + nb1) gemm_body(bx - nb0, p1, dsm);
    else gemm_body(bx - nb0 - nb1, p2, dsm);
}

// ================= szgemm: z-GEMMs (lt, cm) + CSR scatter (4 edge types) =================
__device__ __forceinline__ void scatter_body(int i, const int* __restrict__ src,
                                             const int* __restrict__ dst,
                                             int* __restrict__ cur, int* __restrict__ ss, int E)
{
    if (i >= E) return;
    int d = dst[i];
    int p = atomicAdd(cur + d, 1);
    ss[p] = src[i];
}

__global__ __launch_bounds__(256, 2) void szgemm_kernel(
    GP pz0, GP pz1,
    const int* s0, const int* d0, int* c0, int* x0,
    const int* s1, const int* d1, int* c1, int* x1,
    const int* s2, const int* d2, int* c2, int* x2,
    const int* s3, const int* d3, int* c3, int* x3)
{
    extern __shared__ unsigned short dsm[];
    int bx = blockIdx.x, tid = threadIdx.x;
    if (bx < GB_LT) { gemm_body(bx, pz0, dsm); return; }
    if (bx < GB_LT + GB_CM) { gemm_body(bx - GB_LT, pz1, dsm); return; }
    bx -= GB_LT + GB_CM;
    if (bx < CB0)                 scatter_body(bx * 256 + tid, s0, d0, c0, x0, E0_N);
    else if (bx < CB0 + CB1)      scatter_body((bx - CB0) * 256 + tid, s1, d1, c1, x1, E1_N);
    else if (bx < CB0 + CB1 + CB2) scatter_body((bx - CB0 - CB1) * 256 + tid, s2, d2, c2, x2, E2_N);
    else                          scatter_body((bx - CB0 - CB1 - CB2) * 256 + tid, s3, d3, c3, x3, E3_N);
}

// ---------------- launch ----------------
extern "C" void kernel_launch(void* const* d_in, const int* in_sizes, int n_in,
                              void* d_out, int out_size)
{
    (void)in_sizes; (void)n_in; (void)out_size;
    const float* h0_bv = (const float*)d_in[0];
    const float* h0_lt = (const float*)d_in[1];
    const float* h0_cm = (const float*)d_in[2];
    const float* h0_dn = (const float*)d_in[3];
    const float* ft0 = (const float*)d_in[4];
    const float* ft1 = (const float*)d_in[5];
    const float* ft2 = (const float*)d_in[6];
    const float* ft3 = (const float*)d_in[7];
    const float* convW = (const float*)d_in[8];
    const float* convB = (const float*)d_in[9];
    const float* emlpW = (const float*)d_in[10];
    const float* emlpB = (const float*)d_in[11];
    const float* lng = (const float*)d_in[12];
    const float* lnb = (const float*)d_in[13];
    const int* src0 = (const int*)d_in[14];
    const int* dst0 = (const int*)d_in[15];
    const int* src1 = (const int*)d_in[16];
    const int* dst1 = (const int*)d_in[17];
    const int* src2 = (const int*)d_in[18];
    const int* dst2 = (const int*)d_in[19];
    const int* src3 = (const int*)d_in[20];
    const int* dst3 = (const int*)d_in[21];
    float* out = (float*)d_out;

    cudaFuncSetAttribute(gemm3_kernel, cudaFuncAttributeMaxDynamicSharedMemorySize, GEMM_SMEM);
    cudaFuncSetAttribute(szgemm_kernel, cudaFuncAttributeMaxDynamicSharedMemorySize, GEMM_SMEM);

    float* buf = nullptr;
    cudaGetSymbolAddress((void**)&buf, g_buf);

    __half* mean_bv = (__half*)(buf + OF_MEANBV);
    float* agg2 = buf + OF_AGG2;
    float* agg3 = buf + OF_AGG3;
    float* fts0 = buf + OF_FTS0;
    float* fts1 = buf + OF_FTS1;
    float* fts2 = buf + OF_FTS2;
    float* fts3 = buf + OF_FTS3;
    float* z_lt = buf + OF_ZLT;
    float* z_cm = buf + OF_ZCM;
    float* bias_bv = buf + OF_BBV;
    float* bias_lt = buf + OF_BLT;
    float* bias_cm = buf + OF_BCM;
    __half* dn_h = (__half*)(buf + OF_DNH);
    float* hbv_h = buf + OF_HBVH;
    unsigned short* ws = (unsigned short*)(buf + OF_WS);
    float* bcomb = buf + OF_BCOMB;

    int* icnt0 = (int*)(buf + OF_ICNT0);
    int* icnt1 = (int*)(buf + OF_ICNT1);
    int* icnt2 = (int*)(buf + OF_ICNT2);
    int* icnt3 = (int*)(buf + OF_ICNT3);
    int* P = (int*)(buf + OF_P);
    int* rp0 = (int*)(buf + OF_RP0);
    int* rp1 = (int*)(buf + OF_RP1);
    int* rp2 = (int*)(buf + OF_RP2);
    int* rp3 = (int*)(buf + OF_RP3);
    int* cur0 = (int*)(buf + OF_CUR0);
    int* cur1 = (int*)(buf + OF_CUR1);
    int* cur2 = (int*)(buf + OF_CUR2);
    int* cur3 = (int*)(buf + OF_CUR3);
    int* ss0 = (int*)(buf + OF_SS0);
    int* ss1 = (int*)(buf + OF_SS1);
    int* ss2 = (int*)(buf + OF_SS2);
    int* ss3 = (int*)(buf + OF_SS3);

    float* HBV = buf + OF_HBV;
    float* HLT = buf + OF_HLT;
    float* HCM = buf + OF_HCM;
    float* out_bv = out;
    float* out_lt = out + (size_t)N_BV * D;
    float* out_cm = out + (size_t)(N_BV + N_LT) * D;
    float* out_dn = out + (size_t)(N_BV + N_LT + N_CM) * D;

    unsigned short* ws0 = ws;
    unsigned short* ws1 = ws + (size_t)28 * 8192;

    const __half* zlt_h = (const __half*)z_lt;
    const __half* zcm_h = (const __half*)z_cm;

    // ===== preprocessing =====
    cudaMemsetAsync(buf + OF_FTS0, 0, (OF_ZERO_END - OF_FTS0) * sizeof(float), 0);

    prep_all<<<FB + CVB + CNT_BLKS + 57, 256>>>(
        out_dn, lnb + 384,
        h0_dn, dn_h,
        dst0, ft0, icnt0, fts0,
        dst1, ft1, icnt1, fts1,
        dst2, ft2, icnt2, fts2,
        dst3, ft3, icnt3, fts3,
        convW, convB, ws, bcomb);

    scanbias_all<<<SBB + BIAS_BLKS, 1024>>>(
        icnt0, rp0, cur0, icnt1, rp1, cur1, icnt2, rp2, cur2, icnt3, rp3, cur3, P,
        fts0, icnt0, fts1, icnt1, fts2, icnt2, fts3, icnt3,
        emlpW, emlpB, bias_bv, bias_lt, bias_cm);

    // ===== merged: layer-1 z-GEMMs (fp16 out) + scatter =====
    {
        GP pz0 = {h0_lt, nullptr, N_LT, ws0 + 0 * 8192, 4,
                  nullptr, nullptr, nullptr, nullptr, nullptr, z_lt,
                  nullptr, nullptr, 1, 0, nullptr};
        GP pz1 = {h0_cm, nullptr, N_CM, ws0 + 4 * 8192, 4,
                  nullptr, nullptr, nullptr, nullptr, nullptr, z_cm,
                  nullptr, nullptr, 1, 0, nullptr};
        szgemm_kernel<<<GB_LT + GB_CM + SCT_BLKS, 256, GEMM_SMEM>>>(
            pz0, pz1,
            src0, dst0, cur0, ss0,
            src1, dst1, cur1, ss1,
            src2, dst2, cur2, ss2,
            src3, dst3, cur3, ss3);
    }

    // ===== layer 1 =====
    {
        csr_all_kernel<<<CSRB_ALL, 256>>>(
            rp0, ss0, zlt_h, rp1, ss1, zcm_h, mean_bv,
            rp2, ss2, dn_h, agg2, lnb + 384, 0,
            rp3, ss3, h0_bv, nullptr, 0, agg3);

        GP pl = {h0_lt, agg2, N_LT, ws0 + 12 * 8192, 8,
                 convB + 2 * 128, bias_lt, nullptr, lng + 128, lnb + 128, HLT,
                 ws1 + 0 * 8192, z_lt, 0, 0, nullptr};
        GP pc = {h0_cm, agg3, N_CM, ws0 + 20 * 8192, 8,
                 convB + 3 * 128, bias_cm, nullptr, lng + 256, lnb + 256, HCM,
                 ws1 + 4 * 8192, z_cm, 0, 0, nullptr};
        GP pb = {h0_bv, nullptr, N_BV, ws0 + 8 * 8192, 4,
                 bcomb + 0, (const float*)mean_bv, bias_bv, lng + 0, lnb + 0, HBV,
                 nullptr, nullptr, 0, 1, hbv_h};
        gemm3_kernel<<<GB_LT + GB_CM + GB_BV, 256, GEMM_SMEM>>>(pl, pc, pb, GB_LT, GB_CM);
    }

    // ===== layer 2 (z fp16 from conv1 epilogue; e3 gathers fp16 HBV shadow) =====
    {
        csr_all_kernel<<<CSRB_ALL, 256>>>(
            rp0, ss0, zlt_h, rp1, ss1, zcm_h, mean_bv,
            rp2, ss2, nullptr, agg2, lnb + 384, 1,
            rp3, ss3, nullptr, (const __half*)hbv_h, 1, agg3);

        GP pl = {HLT, agg2, N_LT, ws1 + 12 * 8192, 8,
                 convB + 6 * 128, bias_lt, nullptr, lng + 128, lnb + 128, out_lt,
                 nullptr, nullptr, 0, 0, nullptr};
        GP pc = {HCM, agg3, N_CM, ws1 + 20 * 8192, 8,
                 convB + 7 * 128, bias_cm, nullptr, lng + 256, lnb + 256, out_cm,
                 nullptr, nullptr, 0, 0, nullptr};
        GP pb = {HBV, nullptr, N_BV, ws1 + 8 * 8192, 4,
                 bcomb + 128, (const float*)mean_bv, bias_bv, lng + 0, lnb + 0, out_bv,
                 nullptr, nullptr, 0, 1, nullptr};
        gemm3_kernel<<<GB_LT + GB_CM + GB_BV, 256, GEMM_SMEM>>>(pl, pc, pb, GB_LT, GB_CM);
    }
}

// round 17
// speedup vs baseline: 1.0133x; 1.0133x over previous
#include <cuda_runtime.h>
#include <cuda_bf16.h>
#include <cuda_fp16.h>
#include <cstdint>
#include <cstddef>

#define D 128
#define N_BV 100000
#define N_LT 20000
#define N_CM 2000
#define N_DN 100000
#define E0_N 600000
#define E1_N 200000
#define E2_N 500000
#define E3_N 200000

// ---------------- scratch layout ----------------
constexpr size_t AL(size_t x) { return (x + 31) & ~size_t(31); }
constexpr size_t WS_USHORTS = 2 * 28 * 8192;
constexpr size_t WS_FLOATS  = WS_USHORTS / 2;

constexpr size_t OF_MEANBV = 0;                                   // fp16 payload (N_BV*128 halves)
constexpr size_t OF_AGG2   = AL(OF_MEANBV + (size_t)N_BV * 64);
constexpr size_t OF_AGG3   = AL(OF_AGG2 + (size_t)N_LT * D);
// ---- contiguous zero region: fts0..3, icnt0..3, lookback flags ----
constexpr size_t OF_FTS0   = AL(OF_AGG3 + (size_t)N_CM * D);
constexpr size_t OF_FTS1   = AL(OF_FTS0 + (size_t)N_BV * 16);
constexpr size_t OF_FTS2   = AL(OF_FTS1 + (size_t)N_BV * 16);
constexpr size_t OF_FTS3   = AL(OF_FTS2 + (size_t)N_LT * 16);
constexpr size_t OF_ICNT0  = AL(OF_FTS3 + (size_t)N_CM * 16);
constexpr size_t OF_ICNT1  = AL(OF_ICNT0 + N_BV);
constexpr size_t OF_ICNT2  = AL(OF_ICNT1 + N_BV);
constexpr size_t OF_ICNT3  = AL(OF_ICNT2 + N_LT);
constexpr size_t OF_P      = AL(OF_ICNT3 + N_CM);
constexpr size_t OF_ZERO_END = AL(OF_P + 512);
// ---- rest ----
constexpr size_t OF_HBV    = OF_ZERO_END;
constexpr size_t OF_HLT    = AL(OF_HBV + (size_t)N_BV * D);
constexpr size_t OF_HCM    = AL(OF_HLT + (size_t)N_LT * D);
constexpr size_t OF_ZLT    = AL(OF_HCM + (size_t)N_CM * D);   // fp16 payload
constexpr size_t OF_ZCM    = AL(OF_ZLT + (size_t)N_LT * D);   // fp16 payload
constexpr size_t OF_BBV    = AL(OF_ZCM + (size_t)N_CM * D);
constexpr size_t OF_BLT    = AL(OF_BBV + (size_t)N_BV * D);
constexpr size_t OF_BCM    = AL(OF_BLT + (size_t)N_LT * D);
constexpr size_t OF_WS     = AL(OF_BCM + (size_t)N_CM * D);
constexpr size_t OF_BCOMB  = AL(OF_WS + WS_FLOATS);
constexpr size_t OF_RP0    = AL(OF_BCOMB + 256);
constexpr size_t OF_RP1    = AL(OF_RP0 + N_BV + 1);
constexpr size_t OF_RP2    = AL(OF_RP1 + N_BV + 1);
constexpr size_t OF_RP3    = AL(OF_RP2 + N_LT + 1);
constexpr size_t OF_CUR0   = AL(OF_RP3 + N_CM + 1);
constexpr size_t OF_CUR1   = AL(OF_CUR0 + N_BV);
constexpr size_t OF_CUR2   = AL(OF_CUR1 + N_BV);
constexpr size_t OF_CUR3   = AL(OF_CUR2 + N_LT);
constexpr size_t OF_SS0    = AL(OF_CUR3 + N_CM);
constexpr size_t OF_SS1    = AL(OF_SS0 + E0_N);
constexpr size_t OF_SS2    = AL(OF_SS1 + E1_N);
constexpr size_t OF_SS3    = AL(OF_SS2 + E2_N);
constexpr size_t SCRATCH_TOTAL = OF_SS3 + E3_N + 64;

__device__ __align__(128) float g_buf[SCRATCH_TOTAL];

// ---------------- dispatch constants ----------------
constexpr int CB0 = (E0_N + 255) / 256, CB1 = (E1_N + 255) / 256,
              CB2 = (E2_N + 255) / 256, CB3 = (E3_N + 255) / 256;
constexpr int CNT_BLKS = CB0 + CB1 + CB2 + CB3;
constexpr int SCT_BLKS = CNT_BLKS;
constexpr int FILL4 = (N_DN * D) / 4;
constexpr int FB = (FILL4 + 255) / 256;
constexpr int NB0 = (N_BV + 1023) / 1024, NB1 = NB0,
              NB2 = (N_LT + 1023) / 1024, NB3 = (N_CM + 1023) / 1024;
constexpr int SBB = NB0 + NB1 + NB2 + NB3;
constexpr int GB_BV = (N_BV + 127) / 128, GB_LT = (N_LT + 127) / 128,
              GB_CM = (N_CM + 127) / 128;
constexpr int CSRW_ALL = N_BV + N_LT + N_CM;
constexpr int CSRB_ALL = (CSRW_ALL + 7) / 8;
constexpr int BIAS_ROWS = N_BV + N_LT + N_CM;
constexpr int BIAS_BLKS = (BIAS_ROWS + 7) / 8;
constexpr int GEMM_SMEM = 53248;

// ---------------- helpers ----------------
__device__ __forceinline__ void red_add_v4(float* p, float4 v) {
    asm volatile("red.global.add.v4.f32 [%0], {%1, %2, %3, %4};"
                 :: "l"(p), "f"(v.x), "f"(v.y), "f"(v.z), "f"(v.w)
                 : "memory");
}
__device__ __forceinline__ unsigned short f2bf(float x) {
    __nv_bfloat16 h = __float2bfloat16(x);
    return *reinterpret_cast<unsigned short*>(&h);
}
__device__ __forceinline__ float bf2f(unsigned short u) {
    __nv_bfloat16 h;
    *reinterpret_cast<unsigned short*>(&h) = u;
    return __bfloat162float(h);
}
#define MMA_BF16(d, a0, a1, a2, a3, b0, b1) \
    asm volatile("mma.sync.aligned.m16n8k16.row.col.f32.bf16.bf16.f32 " \
                 "{%0,%1,%2,%3},{%4,%5,%6,%7},{%8,%9},{%0,%1,%2,%3};" \
                 : "+f"(d[0]), "+f"(d[1]), "+f"(d[2]), "+f"(d[3]) \
                 : "r"(a0), "r"(a1), "r"(a2), "r"(a3), "r"(b0), "r"(b1))

// ---------------- CSR gathers: MLP-4, fp32 and fp16 source variants ----------------
__device__ __forceinline__ float4 csr_gather_sum(const int* __restrict__ ss,
                                                 const float* __restrict__ X,
                                                 int b, int e, int lane)
{
    float4 acc = make_float4(0.f, 0.f, 0.f, 0.f);
    int j = b;
    for (; j + 4 <= e; j += 4) {
        int s0 = __ldg(ss + j),     s1 = __ldg(ss + j + 1);
        int s2 = __ldg(ss + j + 2), s3 = __ldg(ss + j + 3);
        float4 v0 = __ldg(reinterpret_cast<const float4*>(X + (size_t)s0 * 128) + lane);
        float4 v1 = __ldg(reinterpret_cast<const float4*>(X + (size_t)s1 * 128) + lane);
        float4 v2 = __ldg(reinterpret_cast<const float4*>(X + (size_t)s2 * 128) + lane);
        float4 v3 = __ldg(reinterpret_cast<const float4*>(X + (size_t)s3 * 128) + lane);
        acc.x += (v0.x + v1.x) + (v2.x + v3.x);
        acc.y += (v0.y + v1.y) + (v2.y + v3.y);
        acc.z += (v0.z + v1.z) + (v2.z + v3.z);
        acc.w += (v0.w + v1.w) + (v2.w + v3.w);
    }
    if (j + 2 <= e) {
        int s0 = __ldg(ss + j), s1 = __ldg(ss + j + 1);
        float4 v0 = __ldg(reinterpret_cast<const float4*>(X + (size_t)s0 * 128) + lane);
        float4 v1 = __ldg(reinterpret_cast<const float4*>(X + (size_t)s1 * 128) + lane);
        acc.x += v0.x + v1.x; acc.y += v0.y + v1.y;
        acc.z += v0.z + v1.z; acc.w += v0.w + v1.w;
        j += 2;
    }
    if (j < e) {
        int s0 = __ldg(ss + j);
        float4 v0 = __ldg(reinterpret_cast<const float4*>(X + (size_t)s0 * 128) + lane);
        acc.x += v0.x; acc.y += v0.y; acc.z += v0.z; acc.w += v0.w;
    }
    return acc;
}

__device__ __forceinline__ void hacc(float4& acc, uint2 u)
{
    float2 f01 = __half22float2(*reinterpret_cast<const __half2*>(&u.x));
    float2 f23 = __half22float2(*reinterpret_cast<const __half2*>(&u.y));
    acc.x += f01.x; acc.y += f01.y; acc.z += f23.x; acc.w += f23.y;
}

__device__ __forceinline__ float4 csr_gather_sum_h(const int* __restrict__ ss,
                                                   const __half* __restrict__ X,
                                                   int b, int e, int lane)
{
    float4 acc = make_float4(0.f, 0.f, 0.f, 0.f);
    int j = b;
    for (; j + 4 <= e; j += 4) {
        int s0 = __ldg(ss + j),     s1 = __ldg(ss + j + 1);
        int s2 = __ldg(ss + j + 2), s3 = __ldg(ss + j + 3);
        uint2 u0 = __ldg(reinterpret_cast<const uint2*>(X + (size_t)s0 * 128) + lane);
        uint2 u1 = __ldg(reinterpret_cast<const uint2*>(X + (size_t)s1 * 128) + lane);
        uint2 u2 = __ldg(reinterpret_cast<const uint2*>(X + (size_t)s2 * 128) + lane);
        uint2 u3 = __ldg(reinterpret_cast<const uint2*>(X + (size_t)s3 * 128) + lane);
        hacc(acc, u0); hacc(acc, u1); hacc(acc, u2); hacc(acc, u3);
    }
    if (j + 2 <= e) {
        int s0 = __ldg(ss + j), s1 = __ldg(ss + j + 1);
        uint2 u0 = __ldg(reinterpret_cast<const uint2*>(X + (size_t)s0 * 128) + lane);
        uint2 u1 = __ldg(reinterpret_cast<const uint2*>(X + (size_t)s1 * 128) + lane);
        hacc(acc, u0); hacc(acc, u1);
        j += 2;
    }
    if (j < e) {
        int s0 = __ldg(ss + j);
        uint2 u0 = __ldg(reinterpret_cast<const uint2*>(X + (size_t)s0 * 128) + lane);
        hacc(acc, u0);
    }
    return acc;
}

__device__ __forceinline__ float4 csr_gather_mean(const int* __restrict__ rp,
                                                  const int* __restrict__ ss,
                                                  const float* __restrict__ X,
                                                  int w, int lane)
{
    int b = rp[w], e = rp[w + 1];
    float4 acc = csr_gather_sum(ss, X, b, e, lane);
    float inv = (e > b) ? 1.0f / (float)(e - b) : 0.0f;
    acc.x *= inv; acc.y *= inv; acc.z *= inv; acc.w *= inv;
    return acc;
}

// ================= prep_all: dn-fill + cnt_ft (4 types) + wsplit + bcomb =================
__device__ __forceinline__ void cnt_ft_body(int i, const int* __restrict__ dst,
                                            const float* __restrict__ ft,
                                            int* __restrict__ icnt, float* __restrict__ fts, int E)
{
    if (i >= E) return;
    int d = dst[i];
    atomicAdd(icnt + d, 1);
    const float4* f = reinterpret_cast<const float4*>(ft) + (size_t)i * 4;
    float* o = fts + (size_t)d * 16;
    red_add_v4(o + 0,  f[0]);
    red_add_v4(o + 4,  f[1]);
    red_add_v4(o + 8,  f[2]);
    red_add_v4(o + 12, f[3]);
}

__global__ void prep_all(
    float* __restrict__ out_dn, const float* __restrict__ lnb3,
    const int* dst0, const float* ft0, int* icnt0, float* fts0,
    const int* dst1, const float* ft1, int* icnt1, float* fts1,
    const int* dst2, const float* ft2, int* icnt2, float* fts2,
    const int* dst3, const float* ft3, int* icnt3, float* fts3,
    const float* __restrict__ convW, const float* __restrict__ convB,
    unsigned short* __restrict__ ws, float* __restrict__ bcomb)
{
    int bx = blockIdx.x, tid = threadIdx.x;
    if (bx < FB) {
        int idx = bx * 256 + tid;
        if (idx < FILL4) {
            float4 v = __ldg(reinterpret_cast<const float4*>(lnb3) + (idx & 31));
            reinterpret_cast<float4*>(out_dn)[idx] = v;
        }
        return;
    }
    bx -= FB;
    if (bx < CNT_BLKS) {
        if (bx < CB0)                 cnt_ft_body(bx * 256 + tid, dst0, ft0, icnt0, fts0, E0_N);
        else if (bx < CB0 + CB1)      cnt_ft_body((bx - CB0) * 256 + tid, dst1, ft1, icnt1, fts1, E1_N);
        else if (bx < CB0 + CB1 + CB2) cnt_ft_body((bx - CB0 - CB1) * 256 + tid, dst2, ft2, icnt2, fts2, E2_N);
        else                          cnt_ft_body((bx - CB0 - CB1 - CB2) * 256 + tid, dst3, ft3, icnt3, fts3, E3_N);
        return;
    }
    bx -= CNT_BLKS;
    if (bx == 56) {
        if (tid < 256) {
            int l = tid >> 7, c = tid & 127;
            bcomb[tid] = convB[(l * 4 + 0) * 128 + c] + convB[(l * 4 + 1) * 128 + c];
        }
        return;
    }
    int l = bx / 28, c = bx % 28;
    const float* Wl = convW + (size_t)l * 4 * 32768;
    unsigned short* wsl = ws + (size_t)l * 28 * 8192;
    const float* W; const float* W2 = nullptr; int chunk; unsigned short* o;
    if (c < 4)       { W = Wl + 16384;             chunk = c;      o = wsl; }
    else if (c < 8)  { W = Wl + 32768 + 16384;     chunk = c - 4;  o = wsl + 4 * 8192; }
    else if (c < 12) { W = Wl; W2 = Wl + 32768;    chunk = c - 8;  o = wsl + 8 * 8192; }
    else if (c < 20) { W = Wl + 2 * 32768;         chunk = c - 12; o = wsl + 12 * 8192; }
    else             { W = Wl + 3 * 32768;         chunk = c - 20; o = wsl + 20 * 8192; }
    int k0 = chunk * 32;
    unsigned short* op = o + (size_t)chunk * 8192;
#pragma unroll
    for (int t = 0; t < 16; t++) {
        int e = tid + t * 256;
        int k = e >> 7;
        int n = e & 127;
        float w = W[(size_t)(k0 + k) * 128 + n];
        if (W2) w += W2[(size_t)(k0 + k) * 128 + n];
        unsigned short hi = f2bf(w);
        unsigned short lo = f2bf(w - bf2f(hi));
        int q = (k & 7) >> 1;
        int slot = k >> 3;
        int off = n * 32 + q * 8 + slot * 2 + (k & 1);
        op[off] = hi;
        op[4096 + off] = lo;
    }
}

// ================= scanbias_all: warp-lookback scan (4 arrays) + edge-bias =================
__global__ void scanbias_all(
    const int* i0, int* r0, int* c0,
    const int* i1, int* r1, int* c1,
    const int* i2, int* r2, int* c2,
    const int* i3, int* r3, int* c3,
    int* __restrict__ P,
    const float* __restrict__ fts0, const int* __restrict__ icnt0,
    const float* __restrict__ fts1, const int* __restrict__ icnt1,
    const float* __restrict__ fts2, const int* __restrict__ icnt2,
    const float* __restrict__ fts3, const int* __restrict__ icnt3,
    const float* __restrict__ emlpW, const float* __restrict__ emlpB,
    float* __restrict__ bias_bv, float* __restrict__ bias_lt, float* __restrict__ bias_cm)
{
    __shared__ int sh[1024];
    __shared__ float fb[8][32];
    __shared__ int s_off;
    int bx = blockIdx.x;
    if (bx < SBB) {
        const int* in; int* outp; int* cur; int n; int lb; int arr; int total;
        if (bx < NB0)                  { in = i0; outp = r0; cur = c0; n = N_BV; lb = bx; arr = 0; total = E0_N; }
        else if (bx < NB0 + NB1)       { in = i1; outp = r1; cur = c1; n = N_BV; lb = bx - NB0; arr = 1; total = E1_N; }
        else if (bx < NB0 + NB1 + NB2) { in = i2; outp = r2; cur = c2; n = N_LT; lb = bx - NB0 - NB1; arr = 2; total = E2_N; }
        else                           { in = i3; outp = r3; cur = c3; n = N_CM; lb = bx - NB0 - NB1 - NB2; arr = 3; total = E3_N; }
        int i = lb * 1024 + threadIdx.x;
        int v = (i < n) ? in[i] : 0;
        sh[threadIdx.x] = v;
        __syncthreads();
        for (int off = 1; off < 1024; off <<= 1) {
            int t = (threadIdx.x >= (unsigned)off) ? sh[threadIdx.x - off] : 0;
            __syncthreads();
            sh[threadIdx.x] += t;
            __syncthreads();
        }
        int incl = sh[threadIdx.x];
        volatile int* Pa = (volatile int*)(P + arr * 128);
        if (threadIdx.x == 1023) {
            __threadfence();
            Pa[lb] = sh[1023] + 1;
        }
        if (threadIdx.x < 32) {
            int off = 0;
            for (int j0 = 0; j0 < lb; j0 += 32) {
                int j = j0 + (int)threadIdx.x;
                int vv = 0;
                if (j < lb) {
                    do { vv = Pa[j]; } while (vv == 0);
                    vv -= 1;
                }
#pragma unroll
                for (int o = 16; o; o >>= 1) vv += __shfl_xor_sync(0xffffffffu, vv, o);
                off += vv;
            }
            if (threadIdx.x == 0) s_off = off;
        }
        __syncthreads();
        int off = s_off;
        if (i < n) {
            int ex = off + incl - v;
            outp[i] = ex;
            cur[i] = ex;
        }
        if (lb == 0 && threadIdx.x == 0) outp[n] = total;
        return;
    }
    // --- bias part ---
    int sub = threadIdx.x >> 7;
    int c = threadIdx.x & 127;
    int row = (bx - SBB) * 8 + sub;
    bool valid = row < BIAS_ROWS;
    if (valid) {
        if (row < N_BV) {
            if (c < 16) fb[sub][c] = fts0[(size_t)row * 16 + c];
            else if (c >= 32 && c < 48) fb[sub][c - 16] = fts1[(size_t)row * 16 + (c - 32)];
        } else if (row < N_BV + N_LT) {
            int r = row - N_BV;
            if (c < 16) fb[sub][c] = fts2[(size_t)r * 16 + c];
        } else {
            int r = row - N_BV - N_LT;
            if (c < 16) fb[sub][c] = fts3[(size_t)r * 16 + c];
        }
    }
    __syncthreads();
    if (!valid) return;
    if (row < N_BV) {
        int c0v = icnt0[row], c1v = icnt1[row];
        float i0v = (c0v > 0) ? 1.0f / (float)c0v : 0.0f;
        float i1v = (c1v > 0) ? 1.0f / (float)c1v : 0.0f;
        float a0 = 0.0f, a1 = 0.0f;
#pragma unroll
        for (int j = 0; j < 16; j++) {
            a0 = fmaf(fb[sub][j],      emlpW[j * 128 + c],        a0);
            a1 = fmaf(fb[sub][16 + j], emlpW[2048 + j * 128 + c], a1);
        }
        float a = a0 * i0v + a1 * i1v;
        if (c0v > 0) a += emlpB[c];
        if (c1v > 0) a += emlpB[128 + c];
        bias_bv[(size_t)row * 128 + c] = a;
    } else {
        const int* icnt; const float* W; const float* bml; float* outp; int r;
        if (row < N_BV + N_LT) {
            r = row - N_BV; icnt = icnt2;
            W = emlpW + 2 * 2048; bml = emlpB + 256; outp = bias_lt;
        } else {
            r = row - N_BV - N_LT; icnt = icnt3;
            W = emlpW + 3 * 2048; bml = emlpB + 384; outp = bias_cm;
        }
        int cv = icnt[r];
        float inv = (cv > 0) ? 1.0f / (float)cv : 0.0f;
        float a = 0.0f;
#pragma unroll
        for (int j = 0; j < 16; j++) a = fmaf(fb[sub][j], W[j * 128 + c], a);
        a *= inv;
        if (cv > 0) a += bml[c];
        outp[(size_t)r * 128 + c] = a;
    }
}

// ---------------- csr_all: cm first, then lt, then bv (mean_bv written fp16) ----------------
__global__ __launch_bounds__(256) void csr_all_kernel(
    const int* __restrict__ rp0, const int* __restrict__ ss0, const __half* __restrict__ X0,
    const int* __restrict__ rp1, const int* __restrict__ ss1, const __half* __restrict__ X1,
    __half* __restrict__ mean_bv,
    const int* __restrict__ rp2, const int* __restrict__ ss2, const float* __restrict__ X2,
    float* __restrict__ agg2, const float* __restrict__ lnb3, int l2mode,
    const int* __restrict__ rp3, const int* __restrict__ ss3, const float* __restrict__ X3,
    float* __restrict__ agg3)
{
    int gw = (int)((blockIdx.x * blockDim.x + threadIdx.x) >> 5);
    int lane = threadIdx.x & 31;
    if (gw < N_CM) {
        float4 a = csr_gather_mean(rp3, ss3, X3, gw, lane);
        reinterpret_cast<float4*>(agg3 + (size_t)gw * 128)[lane] = a;
    } else if (gw < N_CM + N_LT) {
        int w = gw - N_CM;
        if (!l2mode) {
            float4 a = csr_gather_mean(rp2, ss2, X2, w, lane);
            reinterpret_cast<float4*>(agg2 + (size_t)w * 128)[lane] = a;
        } else {
            bool nz = rp2[w + 1] > rp2[w];
            float4 v = make_float4(0.f, 0.f, 0.f, 0.f);
            if (nz) v = __ldg(reinterpret_cast<const float4*>(lnb3) + lane);
            reinterpret_cast<float4*>(agg2 + (size_t)w * 128)[lane] = v;
        }
    } else if (gw < CSRW_ALL) {
        int w = gw - N_CM - N_LT;
        int b0 = rp0[w], e0 = rp0[w + 1];
        int b1 = rp1[w], e1 = rp1[w + 1];
        float4 a = csr_gather_sum_h(ss0, X0, b0, e0, lane);
        float4 b = csr_gather_sum_h(ss1, X1, b1, e1, lane);
        float ia = (e0 > b0) ? 1.0f / (float)(e0 - b0) : 0.0f;
        float ib = (e1 > b1) ? 1.0f / (float)(e1 - b1) : 0.0f;
        a.x = a.x * ia + b.x * ib;
        a.y = a.y * ia + b.y * ib;
        a.z = a.z * ia + b.z * ib;
        a.w = a.w * ia + b.w * ib;
        __half2 h01 = __floats2half2_rn(a.x, a.y);
        __half2 h23 = __floats2half2_rn(a.z, a.w);
        uint2 u;
        u.x = *reinterpret_cast<unsigned*>(&h01);
        u.y = *reinterpret_cast<unsigned*>(&h23);
        *reinterpret_cast<uint2*>(mean_bv + (size_t)w * 128 + lane * 4) = u;
    }
}

// ---------------- tensor-core split-bf16 GEMM core + fused epilogue ----------------
struct GP {
    const float* A1; const float* A2; int M;
    const unsigned short* wsp; int Kc;
    const float* bvec; const float* add1; const float* add2;
    const float* lng; const float* lnb;
    float* C;
    const unsigned short* zwsp;
    float* zC;          // fp16 buffer
    int halfC;          // write C as fp16
    int add1h;          // add1 is fp16
};

__device__ void gemm_core(int row0, const float* __restrict__ A1, const float* __restrict__ A2,
                          int M, const unsigned short* __restrict__ wsp, int Kc,
                          const float* __restrict__ bvec,
                          const float* __restrict__ add1, int add1h,
                          const float* __restrict__ add2,
                          const float* __restrict__ lng, const float* __restrict__ lnb,
                          float* __restrict__ C, int halfout, unsigned short* dsm)
{
    unsigned short (*Ah)[40]  = reinterpret_cast<unsigned short(*)[40]>(dsm);
    unsigned short (*Alo)[40] = reinterpret_cast<unsigned short(*)[40]>(dsm + 5120);
    unsigned short* Bh = dsm + 10240;
    unsigned short* Bl = dsm + 18432;

    int tid = threadIdx.x;
    int wid = tid >> 5, lane = tid & 31;

    float acc[16][4];
#pragma unroll
    for (int i = 0; i < 16; i++)
#pragma unroll
        for (int j = 0; j < 4; j++) acc[i][j] = 0.0f;

    for (int kc = 0; kc < Kc; kc++) {
        const float* Asrc = (kc < 4) ? A1 : A2;
        int kk = (kc & 3) * 32;
#pragma unroll
        for (int t = 0; t < 4; t++) {
            int i = tid + t * 256;
            int r = i >> 3;
            int kq = i & 7;
            int gr = row0 + r;
            float4 v = make_float4(0.f, 0.f, 0.f, 0.f);
            if (gr < M) v = *reinterpret_cast<const float4*>(Asrc + (size_t)gr * 128 + kk + kq * 4);
            unsigned short h0 = f2bf(v.x), h1 = f2bf(v.y), h2 = f2bf(v.z), h3 = f2bf(v.w);
            unsigned short l0 = f2bf(v.x - bf2f(h0)), l1 = f2bf(v.y - bf2f(h1));
            unsigned short l2 = f2bf(v.z - bf2f(h2)), l3 = f2bf(v.w - bf2f(h3));
            *reinterpret_cast<uint2*>(&Ah[r][kq * 4]) =
                make_uint2((uint32_t)h0 | ((uint32_t)h1 << 16), (uint32_t)h2 | ((uint32_t)h3 << 16));
            *reinterpret_cast<uint2*>(&Alo[r][kq * 4]) =
                make_uint2((uint32_t)l0 | ((uint32_t)l1 << 16), (uint32_t)l2 | ((uint32_t)l3 << 16));
        }
        const uint4* wp = reinterpret_cast<const uint4*>(wsp + (size_t)kc * 8192);
        uint4* bhv = reinterpret_cast<uint4*>(Bh);
        uint4* blv = reinterpret_cast<uint4*>(Bl);
#pragma unroll
        for (int t = 0; t < 2; t++) {
            int i = tid + t * 256;
            bhv[i] = wp[i];
            blv[i] = wp[512 + i];
        }
        __syncthreads();

        int ar = wid * 16 + (lane >> 2);
        int q2 = (lane & 3) * 2;
        uint32_t AHr[2][4], ALr[2][4];
#pragma unroll
        for (int ks = 0; ks < 2; ks++) {
            int ac = ks * 16 + q2;
            AHr[ks][0] = *reinterpret_cast<const uint32_t*>(&Ah[ar][ac]);
            AHr[ks][1] = *reinterpret_cast<const uint32_t*>(&Ah[ar + 8][ac]);
            AHr[ks][2] = *reinterpret_cast<const uint32_t*>(&Ah[ar][ac + 8]);
            AHr[ks][3] = *reinterpret_cast<const uint32_t*>(&Ah[ar + 8][ac + 8]);
            ALr[ks][0] = *reinterpret_cast<const uint32_t*>(&Alo[ar][ac]);
            ALr[ks][1] = *reinterpret_cast<const uint32_t*>(&Alo[ar + 8][ac]);
            ALr[ks][2] = *reinterpret_cast<const uint32_t*>(&Alo[ar][ac + 8]);
            ALr[ks][3] = *reinterpret_cast<const uint32_t*>(&Alo[ar + 8][ac + 8]);
        }
#pragma unroll
        for (int nt = 0; nt < 16; nt++) {
            int boff = (nt * 8 + (lane >> 2)) * 32 + (lane & 3) * 8;
            uint4 bh = *reinterpret_cast<const uint4*>(Bh + boff);
            uint4 bl = *reinterpret_cast<const uint4*>(Bl + boff);
            MMA_BF16(acc[nt], AHr[0][0], AHr[0][1], AHr[0][2], AHr[0][3], bh.x, bh.y);
            MMA_BF16(acc[nt], AHr[0][0], AHr[0][1], AHr[0][2], AHr[0][3], bl.x, bl.y);
            MMA_BF16(acc[nt], ALr[0][0], ALr[0][1], ALr[0][2], ALr[0][3], bh.x, bh.y);
            MMA_BF16(acc[nt], AHr[1][0], AHr[1][1], AHr[1][2], AHr[1][3], bh.z, bh.w);
            MMA_BF16(acc[nt], AHr[1][0], AHr[1][1], AHr[1][2], AHr[1][3], bl.z, bl.w);
            MMA_BF16(acc[nt], ALr[1][0], ALr[1][1], ALr[1][2], ALr[1][3], bh.z, bh.w);
        }
        __syncthreads();
    }

    int r1 = row0 + wid * 16 + (lane >> 2);
    int r2 = r1 + 8;
    int cb = (lane & 3) * 2;
    bool ok1 = r1 < M, ok2 = r2 < M;

    float s1 = 0.f, q1 = 0.f, s2 = 0.f, q2s = 0.f;
#pragma unroll
    for (int nt = 0; nt < 16; nt++) {
        int col = nt * 8 + cb;
        if (bvec) {
            float bx = bvec[col], by = bvec[col + 1];
            acc[nt][0] += bx; acc[nt][1] += by;
            acc[nt][2] += bx; acc[nt][3] += by;
        }
        if (add1) {
            if (add1h) {
                const __half* A1h = reinterpret_cast<const __half*>(add1);
                if (ok1) {
                    __half2 q = *reinterpret_cast<const __half2*>(A1h + (size_t)r1 * 128 + col);
                    float2 f = __half22float2(q);
                    acc[nt][0] += f.x; acc[nt][1] += f.y;
                }
                if (ok2) {
                    __half2 q = *reinterpret_cast<const __half2*>(A1h + (size_t)r2 * 128 + col);
                    float2 f = __half22float2(q);
                    acc[nt][2] += f.x; acc[nt][3] += f.y;
                }
            } else {
                if (ok1) {
                    float2 q = *reinterpret_cast<const float2*>(add1 + (size_t)r1 * 128 + col);
                    acc[nt][0] += q.x; acc[nt][1] += q.y;
                }
                if (ok2) {
                    float2 q = *reinterpret_cast<const float2*>(add1 + (size_t)r2 * 128 + col);
                    acc[nt][2] += q.x; acc[nt][3] += q.y;
                }
            }
        }
        if (add2) {
            if (ok1) {
                float2 q = *reinterpret_cast<const float2*>(add2 + (size_t)r1 * 128 + col);
                acc[nt][0] += q.x; acc[nt][1] += q.y;
            }
            if (ok2) {
                float2 q = *reinterpret_cast<const float2*>(add2 + (size_t)r2 * 128 + col);
                acc[nt][2] += q.x; acc[nt][3] += q.y;
            }
        }
        s1 += acc[nt][0] + acc[nt][1];
        q1 += acc[nt][0] * acc[nt][0] + acc[nt][1] * acc[nt][1];
        s2 += acc[nt][2] + acc[nt][3];
        q2s += acc[nt][2] * acc[nt][2] + acc[nt][3] * acc[nt][3];
    }

    float m1 = 0.f, rs1 = 1.f, m2 = 0.f, rs2 = 1.f;
    if (lng) {
#pragma unroll
        for (int off = 1; off < 4; off <<= 1) {
            s1 += __shfl_xor_sync(0xffffffffu, s1, off);
            q1 += __shfl_xor_sync(0xffffffffu, q1, off);
            s2 += __shfl_xor_sync(0xffffffffu, s2, off);
            q2s += __shfl_xor_sync(0xffffffffu, q2s, off);
        }
        m1 = s1 * (1.0f / 128.0f);
        rs1 = rsqrtf(q1 * (1.0f / 128.0f) - m1 * m1 + 1e-5f);
        m2 = s2 * (1.0f / 128.0f);
        rs2 = rsqrtf(q2s * (1.0f / 128.0f) - m2 * m2 + 1e-5f);
    }

#pragma unroll
    for (int nt = 0; nt < 16; nt++) {
        int col = nt * 8 + cb;
        float o0 = acc[nt][0], o1 = acc[nt][1], o2 = acc[nt][2], o3 = acc[nt][3];
        if (lng) {
            float gx = lng[col], gy = lng[col + 1];
            float bx = lnb[col], by = lnb[col + 1];
            o0 = (o0 - m1) * rs1 * gx + bx;
            o1 = (o1 - m1) * rs1 * gy + by;
            o2 = (o2 - m2) * rs2 * gx + bx;
            o3 = (o3 - m2) * rs2 * gy + by;
        }
        if (halfout) {
            __half* Ch = reinterpret_cast<__half*>(C);
            if (ok1) *reinterpret_cast<__half2*>(Ch + (size_t)r1 * 128 + col) = __floats2half2_rn(o0, o1);
            if (ok2) *reinterpret_cast<__half2*>(Ch + (size_t)r2 * 128 + col) = __floats2half2_rn(o2, o3);
        } else {
            if (ok1) *reinterpret_cast<float2*>(C + (size_t)r1 * 128 + col) = make_float2(o0, o1);
            if (ok2) *reinterpret_cast<float2*>(C + (size_t)r2 * 128 + col) = make_float2(o2, o3);
        }
    }
}

__device__ void gemm_body(int blk, const GP& p, unsigned short* dsm)
{
    gemm_core(blk * 128, p.A1, p.A2, p.M, p.wsp, p.Kc,
              p.bvec, p.add1, p.add1h, p.add2, p.lng, p.lnb, p.C, p.halfC, dsm);
    if (p.zwsp) {
        __threadfence_block();
        __syncthreads();
        gemm_core(blk * 128, p.C, nullptr, p.M, p.zwsp, 4,
                  nullptr, nullptr, 0, nullptr, nullptr, nullptr, p.zC, 1, dsm);
    }
}

__global__ __launch_bounds__(256, 2) void gemm3_kernel(GP p0, GP p1, GP p2, int nb0, int nb1)
{
    extern __shared__ unsigned short dsm[];
    int bx = blockIdx.x;
    if (bx < nb0) gemm_body(bx, p0, dsm);
    else if (bx < nb0 + nb1) gemm_body(bx - nb0, p1, dsm);
    else gemm_body(bx - nb0 - nb1, p2, dsm);
}

// ================= szgemm: z-GEMMs (lt, cm) + CSR scatter (4 edge types) =================
__device__ __forceinline__ void scatter_body(int i, const int* __restrict__ src,
                                             const int* __restrict__ dst,
                                             int* __restrict__ cur, int* __restrict__ ss, int E)
{
    if (i >= E) return;
    int d = dst[i];
    int p = atomicAdd(cur + d, 1);
    ss[p] = src[i];
}

__global__ __launch_bounds__(256, 2) void szgemm_kernel(
    GP pz0, GP pz1,
    const int* s0, const int* d0, int* c0, int* x0,
    const int* s1, const int* d1, int* c1, int* x1,
    const int* s2, const int* d2, int* c2, int* x2,
    const int* s3, const int* d3, int* c3, int* x3)
{
    extern __shared__ unsigned short dsm[];
    int bx = blockIdx.x, tid = threadIdx.x;
    if (bx < GB_LT) { gemm_body(bx, pz0, dsm); return; }
    if (bx < GB_LT + GB_CM) { gemm_body(bx - GB_LT, pz1, dsm); return; }
    bx -= GB_LT + GB_CM;
    if (bx < CB0)                 scatter_body(bx * 256 + tid, s0, d0, c0, x0, E0_N);
    else if (bx < CB0 + CB1)      scatter_body((bx - CB0) * 256 + tid, s1, d1, c1, x1, E1_N);
    else if (bx < CB0 + CB1 + CB2) scatter_body((bx - CB0 - CB1) * 256 + tid, s2, d2, c2, x2, E2_N);
    else                          scatter_body((bx - CB0 - CB1 - CB2) * 256 + tid, s3, d3, c3, x3, E3_N);
}

// ---------------- launch ----------------
extern "C" void kernel_launch(void* const* d_in, const int* in_sizes, int n_in,
                              void* d_out, int out_size)
{
    (void)in_sizes; (void)n_in; (void)out_size;
    const float* h0_bv = (const float*)d_in[0];
    const float* h0_lt = (const float*)d_in[1];
    const float* h0_cm = (const float*)d_in[2];
    const float* h0_dn = (const float*)d_in[3];
    const float* ft0 = (const float*)d_in[4];
    const float* ft1 = (const float*)d_in[5];
    const float* ft2 = (const float*)d_in[6];
    const float* ft3 = (const float*)d_in[7];
    const float* convW = (const float*)d_in[8];
    const float* convB = (const float*)d_in[9];
    const float* emlpW = (const float*)d_in[10];
    const float* emlpB = (const float*)d_in[11];
    const float* lng = (const float*)d_in[12];
    const float* lnb = (const float*)d_in[13];
    const int* src0 = (const int*)d_in[14];
    const int* dst0 = (const int*)d_in[15];
    const int* src1 = (const int*)d_in[16];
    const int* dst1 = (const int*)d_in[17];
    const int* src2 = (const int*)d_in[18];
    const int* dst2 = (const int*)d_in[19];
    const int* src3 = (const int*)d_in[20];
    const int* dst3 = (const int*)d_in[21];
    float* out = (float*)d_out;

    cudaFuncSetAttribute(gemm3_kernel, cudaFuncAttributeMaxDynamicSharedMemorySize, GEMM_SMEM);
    cudaFuncSetAttribute(szgemm_kernel, cudaFuncAttributeMaxDynamicSharedMemorySize, GEMM_SMEM);

    float* buf = nullptr;
    cudaGetSymbolAddress((void**)&buf, g_buf);

    __half* mean_bv = (__half*)(buf + OF_MEANBV);
    float* agg2 = buf + OF_AGG2;
    float* agg3 = buf + OF_AGG3;
    float* fts0 = buf + OF_FTS0;
    float* fts1 = buf + OF_FTS1;
    float* fts2 = buf + OF_FTS2;
    float* fts3 = buf + OF_FTS3;
    float* z_lt = buf + OF_ZLT;
    float* z_cm = buf + OF_ZCM;
    float* bias_bv = buf + OF_BBV;
    float* bias_lt = buf + OF_BLT;
    float* bias_cm = buf + OF_BCM;
    unsigned short* ws = (unsigned short*)(buf + OF_WS);
    float* bcomb = buf + OF_BCOMB;

    int* icnt0 = (int*)(buf + OF_ICNT0);
    int* icnt1 = (int*)(buf + OF_ICNT1);
    int* icnt2 = (int*)(buf + OF_ICNT2);
    int* icnt3 = (int*)(buf + OF_ICNT3);
    int* P = (int*)(buf + OF_P);
    int* rp0 = (int*)(buf + OF_RP0);
    int* rp1 = (int*)(buf + OF_RP1);
    int* rp2 = (int*)(buf + OF_RP2);
    int* rp3 = (int*)(buf + OF_RP3);
    int* cur0 = (int*)(buf + OF_CUR0);
    int* cur1 = (int*)(buf + OF_CUR1);
    int* cur2 = (int*)(buf + OF_CUR2);
    int* cur3 = (int*)(buf + OF_CUR3);
    int* ss0 = (int*)(buf + OF_SS0);
    int* ss1 = (int*)(buf + OF_SS1);
    int* ss2 = (int*)(buf + OF_SS2);
    int* ss3 = (int*)(buf + OF_SS3);

    float* HBV = buf + OF_HBV;
    float* HLT = buf + OF_HLT;
    float* HCM = buf + OF_HCM;
    float* out_bv = out;
    float* out_lt = out + (size_t)N_BV * D;
    float* out_cm = out + (size_t)(N_BV + N_LT) * D;
    float* out_dn = out + (size_t)(N_BV + N_LT + N_CM) * D;

    unsigned short* ws0 = ws;
    unsigned short* ws1 = ws + (size_t)28 * 8192;

    const __half* zlt_h = (const __half*)z_lt;
    const __half* zcm_h = (const __half*)z_cm;

    // ===== preprocessing =====
    cudaMemsetAsync(buf + OF_FTS0, 0, (OF_ZERO_END - OF_FTS0) * sizeof(float), 0);

    prep_all<<<FB + CNT_BLKS + 57, 256>>>(
        out_dn, lnb + 384,
        dst0, ft0, icnt0, fts0,
        dst1, ft1, icnt1, fts1,
        dst2, ft2, icnt2, fts2,
        dst3, ft3, icnt3, fts3,
        convW, convB, ws, bcomb);

    scanbias_all<<<SBB + BIAS_BLKS, 1024>>>(
        icnt0, rp0, cur0, icnt1, rp1, cur1, icnt2, rp2, cur2, icnt3, rp3, cur3, P,
        fts0, icnt0, fts1, icnt1, fts2, icnt2, fts3, icnt3,
        emlpW, emlpB, bias_bv, bias_lt, bias_cm);

    // ===== merged: layer-1 z-GEMMs (fp16 out) + scatter =====
    {
        GP pz0 = {h0_lt, nullptr, N_LT, ws0 + 0 * 8192, 4,
                  nullptr, nullptr, nullptr, nullptr, nullptr, z_lt,
                  nullptr, nullptr, 1, 0};
        GP pz1 = {h0_cm, nullptr, N_CM, ws0 + 4 * 8192, 4,
                  nullptr, nullptr, nullptr, nullptr, nullptr, z_cm,
                  nullptr, nullptr, 1, 0};
        szgemm_kernel<<<GB_LT + GB_CM + SCT_BLKS, 256, GEMM_SMEM>>>(
            pz0, pz1,
            src0, dst0, cur0, ss0,
            src1, dst1, cur1, ss1,
            src2, dst2, cur2, ss2,
            src3, dst3, cur3, ss3);
    }

    // ===== layer 1 =====
    {
        csr_all_kernel<<<CSRB_ALL, 256>>>(
            rp0, ss0, zlt_h, rp1, ss1, zcm_h, mean_bv,
            rp2, ss2, h0_dn, agg2, lnb + 384, 0,
            rp3, ss3, h0_bv, agg3);

        GP pl = {h0_lt, agg2, N_LT, ws0 + 12 * 8192, 8,
                 convB + 2 * 128, bias_lt, nullptr, lng + 128, lnb + 128, HLT,
                 ws1 + 0 * 8192, z_lt, 0, 0};
        GP pc = {h0_cm, agg3, N_CM, ws0 + 20 * 8192, 8,
                 convB + 3 * 128, bias_cm, nullptr, lng + 256, lnb + 256, HCM,
                 ws1 + 4 * 8192, z_cm, 0, 0};
        GP pb = {h0_bv, nullptr, N_BV, ws0 + 8 * 8192, 4,
                 bcomb + 0, (const float*)mean_bv, bias_bv, lng + 0, lnb + 0, HBV,
                 nullptr, nullptr, 0, 1};
        gemm3_kernel<<<GB_LT + GB_CM + GB_BV, 256, GEMM_SMEM>>>(pl, pc, pb, GB_LT, GB_CM);
    }

    // ===== layer 2 (z fp16 from conv1 epilogue) =====
    {
        csr_all_kernel<<<CSRB_ALL, 256>>>(
            rp0, ss0, zlt_h, rp1, ss1, zcm_h, mean_bv,
            rp2, ss2, nullptr, agg2, lnb + 384, 1,
            rp3, ss3, HBV, agg3);

        GP pl = {HLT, agg2, N_LT, ws1 + 12 * 8192, 8,
                 convB + 6 * 128, bias_lt, nullptr, lng + 128, lnb + 128, out_lt,
                 nullptr, nullptr, 0, 0};
        GP pc = {HCM, agg3, N_CM, ws1 + 20 * 8192, 8,
                 convB + 7 * 128, bias_cm, nullptr, lng + 256, lnb + 256, out_cm,
                 nullptr, nullptr, 0, 0};
        GP pb = {HBV, nullptr, N_BV, ws1 + 8 * 8192, 4,
                 bcomb + 128, (const float*)mean_bv, bias_bv, lng + 0, lnb + 0, out_bv,
                 nullptr, nullptr, 0, 1};
        gemm3_kernel<<<GB_LT + GB_CM + GB_BV, 256, GEMM_SMEM>>>(pl, pc, pb, GB_LT, GB_CM);
    }
}